// round 9
// baseline (speedup 1.0000x reference)
#include <cuda_runtime.h>
#include <cuda_fp16.h>

#define TSEQ   4096
#define DMODEL 512
#define NHEADS 8
#define DKH    64
#define NBATCH 2
#define MTOT   (NBATCH*TSEQ)          // 8192
// 1/sqrt(64) * log2(e): folded into Q so S is in log2 domain -> p = exp2(S)
#define QSC    0.1803368801111601f

// Scratch (allocation-free rule: static device globals)
__device__ __half g_xh[(size_t)MTOT*DMODEL];              // x in fp16
__device__ __half g_wh[4][(size_t)DMODEL*DMODEL];         // Wq,Wk,Wv,Wo in fp16
__device__ __half g_qh[(size_t)NBATCH*NHEADS*TSEQ*DKH];   // [B,H,T,dk] fp16 (Q pre-scaled)
__device__ __half g_kh[(size_t)NBATCH*NHEADS*TSEQ*DKH];
__device__ __half g_vh[(size_t)NBATCH*NHEADS*TSEQ*DKH];
__device__ __half g_oh[(size_t)MTOT*DMODEL];              // attention out fp16

__device__ __forceinline__ void mmah(float* d, const unsigned* a, const unsigned* b) {
    asm("mma.sync.aligned.m16n8k16.row.col.f32.f16.f16.f32 "
        "{%0,%1,%2,%3},{%4,%5,%6,%7},{%8,%9},{%0,%1,%2,%3};"
        : "+f"(d[0]), "+f"(d[1]), "+f"(d[2]), "+f"(d[3])
        : "r"(a[0]), "r"(a[1]), "r"(a[2]), "r"(a[3]), "r"(b[0]), "r"(b[1]));
}

// fp16-accumulator variant: C/D are 2 regs of packed half2 (rows r / r+8,
// col pairs (2cl, 2cl+1)) — exactly the PV A-fragment k-pair layout.
__device__ __forceinline__ void mmah16(unsigned* d, const unsigned* a, const unsigned* b) {
    asm("mma.sync.aligned.m16n8k16.row.col.f16.f16.f16.f16 "
        "{%0,%1},{%2,%3,%4,%5},{%6,%7},{%0,%1};"
        : "+r"(d[0]), "+r"(d[1])
        : "r"(a[0]), "r"(a[1]), "r"(a[2]), "r"(a[3]), "r"(b[0]), "r"(b[1]));
}

__device__ __forceinline__ unsigned h2exp2u(unsigned x) {
    unsigned r;
    asm("ex2.approx.f16x2 %0, %1;" : "=r"(r) : "r"(x));
    return r;
}

__device__ __forceinline__ void ldm_x4(unsigned* q, unsigned addr) {
    asm volatile("ldmatrix.sync.aligned.m8n8.x4.shared.b16 {%0,%1,%2,%3}, [%4];"
                 : "=r"(q[0]), "=r"(q[1]), "=r"(q[2]), "=r"(q[3]) : "r"(addr));
}
__device__ __forceinline__ void ldm_x2(unsigned& b0, unsigned& b1, unsigned addr) {
    asm volatile("ldmatrix.sync.aligned.m8n8.x2.shared.b16 {%0,%1}, [%2];"
                 : "=r"(b0), "=r"(b1) : "r"(addr));
}
__device__ __forceinline__ void ldm_x2_t(unsigned& b0, unsigned& b1, unsigned addr) {
    asm volatile("ldmatrix.sync.aligned.m8n8.x2.trans.shared.b16 {%0,%1}, [%2];"
                 : "=r"(b0), "=r"(b1) : "r"(addr));
}

#define CP_ASYNC16(dst, src) \
    asm volatile("cp.async.ca.shared.global [%0], [%1], 16;" :: "r"(dst), "l"(src) : "memory")
#define CP_COMMIT   asm volatile("cp.async.commit_group;" ::: "memory")
#define CP_WAIT0    asm volatile("cp.async.wait_group 0;" ::: "memory")
#define CP_WAIT1    asm volatile("cp.async.wait_group 1;" ::: "memory")

// ---------------------------------------------------------------------------
// Fused fp32 -> fp16 conversion: x + 4 weights
// ---------------------------------------------------------------------------
#define XF4 (MTOT * DMODEL / 4)        // 1048576
#define WF4 (DMODEL * DMODEL / 4)      // 65536
#define CVT_TOT (XF4 + 4 * WF4)

__global__ __launch_bounds__(256)
void cvt_all_kernel(const float* __restrict__ x,
                    const float* __restrict__ w0, const float* __restrict__ w1,
                    const float* __restrict__ w2, const float* __restrict__ w3)
{
    const int i = blockIdx.x * 256 + threadIdx.x;
    if (i >= CVT_TOT) return;
    const float* s;
    __half* d;
    int off;
    if (i < XF4) {
        s = x; d = g_xh; off = i;
    } else {
        const int j = i - XF4;
        const int wsel = j >> 16;
        off = j & (WF4 - 1);
        s = (wsel == 0) ? w0 : (wsel == 1) ? w1 : (wsel == 2) ? w2 : w3;
        d = g_wh[wsel];
    }
    const float4 v = *(const float4*)(s + 4 * (size_t)off);
    half2 a = __floats2half2_rn(v.x, v.y);
    half2 b = __floats2half2_rn(v.z, v.w);
    *(uint2*)(d + 4 * (size_t)off) = make_uint2(*(unsigned*)&a, *(unsigned*)&b);
}

// ---------------------------------------------------------------------------
// fp16 NT GEMM body (unchanged): CTA 128x128, BK=64, 8 warps, m16n8k16,
// cp.async double-buffered, stride-72 smem rows.
// ---------------------------------------------------------------------------
#define GSTRH 72
#define GTILE (128 * GSTRH)
#define GEMM_SMEM (4 * GTILE * 2)      // 73728 B

__device__ __forceinline__ void gemm_body_fp16(
    const __half* __restrict__ A, const __half* __restrict__ W,
    float (&acc)[4][4][4], __half* smh, int m0, int n0, int tid)
{
    const unsigned smb = (unsigned)__cvta_generic_to_shared(smh);
    const int lane = tid & 31, wid = tid >> 5;
    const int wm = wid >> 2, wn = wid & 3;
    const int l15 = lane & 15, l16 = lane >> 4;
    const int l7 = lane & 7,  l8 = (lane >> 3) & 1;

    const int crow = tid >> 1;
    const int cseg = (tid & 1) * 32;

    const __half* Asrc = A + (size_t)(m0 + crow) * DMODEL + cseg;
    const __half* Wsrc = W + (size_t)(n0 + crow) * DMODEL + cseg;
    const unsigned adst = smb + (unsigned)(crow * GSTRH + cseg) * 2;
    const unsigned bdst = adst + GTILE * 2;

    #pragma unroll
    for (int i = 0; i < 4; ++i) {
        CP_ASYNC16(adst + 16 * i, Asrc + 8 * i);
        CP_ASYNC16(bdst + 16 * i, Wsrc + 8 * i);
    }
    CP_COMMIT;

    const unsigned afl = (unsigned)(l15 * GSTRH + l16 * 8) * 2;
    const unsigned bfl = (unsigned)(l7 * GSTRH + l8 * 8) * 2;

    const int NK = DMODEL / 64;
    for (int ks = 0; ks < NK; ++ks) {
        const int st = ks & 1;
        if (ks + 1 < NK) {
            const unsigned base = smb + (unsigned)(st ^ 1) * (2 * GTILE * 2);
            const unsigned ad = base + (unsigned)(crow * GSTRH + cseg) * 2;
            const unsigned bd = ad + GTILE * 2;
            const __half* as = Asrc + (ks + 1) * 64;
            const __half* ws = Wsrc + (ks + 1) * 64;
            #pragma unroll
            for (int i = 0; i < 4; ++i) {
                CP_ASYNC16(ad + 16 * i, as + 8 * i);
                CP_ASYNC16(bd + 16 * i, ws + 8 * i);
            }
            CP_COMMIT;
            CP_WAIT1;
        } else {
            CP_WAIT0;
        }
        __syncthreads();

        const unsigned abase = smb + (unsigned)st * (2 * GTILE * 2);
        const unsigned bbase = abase + GTILE * 2;

        #pragma unroll
        for (int kc = 0; kc < 4; ++kc) {
            unsigned a[4][4], b[4][2];
            #pragma unroll
            for (int mt = 0; mt < 4; ++mt)
                ldm_x4(a[mt], abase + (unsigned)((wm * 64 + mt * 16) * GSTRH + kc * 16) * 2 + afl);
            #pragma unroll
            for (int nt = 0; nt < 4; ++nt)
                ldm_x2(b[nt][0], b[nt][1],
                       bbase + (unsigned)((wn * 32 + nt * 8) * GSTRH + kc * 16) * 2 + bfl);
            #pragma unroll
            for (int mt = 0; mt < 4; ++mt)
                #pragma unroll
                for (int nt = 0; nt < 4; ++nt)
                    mmah(acc[mt][nt], a[mt], b[nt]);
        }
        __syncthreads();
    }
}

__global__ __launch_bounds__(256, 2)
void qkv_gemm_kernel(int dummy)
{
    extern __shared__ __half smh[];
    const __half* W = g_wh[blockIdx.z];
    __half* dst = (blockIdx.z == 0) ? g_qh : (blockIdx.z == 1) ? g_kh : g_vh;
    const float sc = (blockIdx.z == 0) ? QSC : 1.0f;

    const int tid = threadIdx.x;
    const int lane = tid & 31, wid = tid >> 5;
    const int wm = wid >> 2, wn = wid & 3;
    const int r = lane >> 2, cl = lane & 3;
    const int m0 = blockIdx.x * 128, n0 = blockIdx.y * 128;

    float acc[4][4][4] = {};
    gemm_body_fp16(g_xh, W, acc, smh, m0, n0, tid);

    #pragma unroll
    for (int mt = 0; mt < 4; ++mt) {
        #pragma unroll
        for (int half_ = 0; half_ < 2; ++half_) {
            const int m = m0 + wm * 64 + mt * 16 + r + half_ * 8;
            const int b = m >> 12;
            const int t = m & 4095;
            #pragma unroll
            for (int nt = 0; nt < 4; ++nt) {
                const int n = n0 + wn * 32 + nt * 8 + 2 * cl;
                const int h = n >> 6, d = n & 63;
                const float vx = (half_ ? acc[mt][nt][2] : acc[mt][nt][0]) * sc;
                const float vy = (half_ ? acc[mt][nt][3] : acc[mt][nt][1]) * sc;
                *(half2*)&dst[(((size_t)(b * NHEADS + h) * TSEQ) + t) * DKH + d] =
                    __floats2half2_rn(vx, vy);
            }
        }
    }
    (void)dummy;
}

__global__ __launch_bounds__(256, 2)
void proj_gemm_kernel(float* __restrict__ out)
{
    extern __shared__ __half smh[];
    const int tid = threadIdx.x;
    const int lane = tid & 31, wid = tid >> 5;
    const int wm = wid >> 2, wn = wid & 3;
    const int r = lane >> 2, cl = lane & 3;
    const int m0 = blockIdx.x * 128, n0 = blockIdx.y * 128;

    float acc[4][4][4] = {};
    gemm_body_fp16(g_oh, g_wh[3], acc, smh, m0, n0, tid);

    #pragma unroll
    for (int mt = 0; mt < 4; ++mt) {
        const int m = m0 + wm * 64 + mt * 16 + r;
        #pragma unroll
        for (int nt = 0; nt < 4; ++nt) {
            const int n = n0 + wn * 32 + nt * 8 + 2 * cl;
            *(float2*)&out[(size_t)m * DMODEL + n] =
                make_float2(acc[mt][nt][0], acc[mt][nt][1]);
            *(float2*)&out[(size_t)(m + 8) * DMODEL + n] =
                make_float2(acc[mt][nt][2], acc[mt][nt][3]);
        }
    }
}

// ---------------------------------------------------------------------------
// Flash attention, fully-fp16 score path:
//   S accumulated in fp16 (packed C-frags == PV A-frag layout, zero reshapes)
//   p = ex2.approx.f16x2(S)  (S in log2 domain via QSC)
//   row sums li via ones-MMA with fp32 accumulate (consistent normalization)
// Br=256 (8 warps x 32 rows), Bc=128, cp.async double-buffered, 2 CTAs/SM.
// ---------------------------------------------------------------------------
#define HSTR 72
#define BUFH (256 * HSTR)
#define FLASH_SMEM (2 * BUFH * 2)      // 73728 B
#define ONES_H2 0x3C003C00u            // half2(1.0, 1.0)

__global__ __launch_bounds__(256, 2)
void flash_kernel()
{
    extern __shared__ __half smh[];
    const unsigned smb = (unsigned)__cvta_generic_to_shared(smh);

    const int tid  = threadIdx.x;
    const int lane = tid & 31, wid = tid >> 5;
    const int r = lane >> 2, cl = lane & 3;
    const int l7 = lane & 7, l8 = (lane >> 3) & 1;
    const int qb = blockIdx.x, h = blockIdx.y, b = blockIdx.z;

    const __half* Qg = g_qh + (((size_t)(b * NHEADS + h) * TSEQ) + qb * 256) * DKH;
    const __half* Kg = g_kh + ((size_t)(b * NHEADS + h) * TSEQ) * DKH;
    const __half* Vg = g_vh + ((size_t)(b * NHEADS + h) * TSEQ) * DKH;

    // ---- stage Q tile (256x64 fp16), extract A-frags ----
    {
        const uint4* qsrc = (const uint4*)(Qg + (size_t)tid * DKH);
        uint4* qdst = (uint4*)(smh + tid * HSTR);
        #pragma unroll
        for (int i = 0; i < 8; ++i) qdst[i] = qsrc[i];
    }
    __syncthreads();

    unsigned qa[2][4][4];
    #pragma unroll
    for (int mt = 0; mt < 2; ++mt) {
        const int row = wid * 32 + mt * 16 + r;
        #pragma unroll
        for (int kc = 0; kc < 4; ++kc) {
            qa[mt][kc][0] = *(const unsigned*)&smh[row * HSTR + 16 * kc + 2 * cl];
            qa[mt][kc][1] = *(const unsigned*)&smh[(row + 8) * HSTR + 16 * kc + 2 * cl];
            qa[mt][kc][2] = *(const unsigned*)&smh[row * HSTR + 16 * kc + 2 * cl + 8];
            qa[mt][kc][3] = *(const unsigned*)&smh[(row + 8) * HSTR + 16 * kc + 2 * cl + 8];
        }
    }
    __syncthreads();

    const int crow = tid & 127;
    const bool isV = tid >= 128;
    const __half* gsrc0 = isV ? Vg : Kg;
    const unsigned dst_off = ((isV ? 128 * HSTR : 0) + crow * HSTR) * 2;

    {   // prologue
        const __half* src = gsrc0 + (size_t)crow * DKH;
        const unsigned d0 = smb + dst_off;
        #pragma unroll
        for (int i = 0; i < 8; ++i) CP_ASYNC16(d0 + 16 * i, src + 8 * i);
        CP_COMMIT;
    }

    float oacc[2][8][4] = {};
    float lacc[2][4] = {};
    const unsigned onesb[2] = {ONES_H2, ONES_H2};

    const unsigned kla = (unsigned)(l7 * HSTR + l8 * 8) * 2;
    const unsigned vla = (unsigned)((l7 + 8 * l8) * HSTR) * 2;

    const int NT = TSEQ / 128;
    for (int kt = 0; kt < NT; ++kt) {
        const int bf = kt & 1;
        if (kt + 1 < NT) {
            const __half* src = gsrc0 + (size_t)((kt + 1) * 128 + crow) * DKH;
            const unsigned d0 = smb + (unsigned)(bf ^ 1) * (BUFH * 2) + dst_off;
            #pragma unroll
            for (int i = 0; i < 8; ++i) CP_ASYNC16(d0 + 16 * i, src + 8 * i);
            CP_COMMIT;
            CP_WAIT1;
        } else {
            CP_WAIT0;
        }
        __syncthreads();

        const unsigned kbase = smb + (unsigned)bf * (BUFH * 2);
        const unsigned vbase = kbase + 128 * HSTR * 2;

        #pragma unroll
        for (int ch = 0; ch < 2; ++ch) {
            // ---- S chunk (log2 domain), fp16 accumulators ----
            unsigned sacc[2][8][2] = {};
            #pragma unroll
            for (int t = 0; t < 8; ++t) {
                const unsigned rowb = kbase + (unsigned)((64 * ch + 8 * t) * HSTR) * 2 + kla;
                #pragma unroll
                for (int kc = 0; kc < 4; ++kc) {
                    unsigned bb[2];
                    ldm_x2(bb[0], bb[1], rowb + 32 * kc);
                    mmah16(sacc[0][t], qa[0][kc], bb);
                    mmah16(sacc[1][t], qa[1][kc], bb);
                }
            }

            // ---- PV: pa = exp2(S) straight from packed C-frags ----
            #pragma unroll
            for (int kc = 0; kc < 4; ++kc) {
                unsigned pa[2][4];
                #pragma unroll
                for (int mt = 0; mt < 2; ++mt) {
                    pa[mt][0] = h2exp2u(sacc[mt][2*kc][0]);
                    pa[mt][1] = h2exp2u(sacc[mt][2*kc][1]);
                    pa[mt][2] = h2exp2u(sacc[mt][2*kc + 1][0]);
                    pa[mt][3] = h2exp2u(sacc[mt][2*kc + 1][1]);
                }
                mmah(lacc[0], pa[0], onesb);
                mmah(lacc[1], pa[1], onesb);
                const unsigned vrow = vbase + (unsigned)((64 * ch + 16 * kc) * HSTR) * 2 + vla;
                #pragma unroll
                for (int n = 0; n < 8; ++n) {
                    unsigned bb[2];
                    ldm_x2_t(bb[0], bb[1], vrow + 16 * n);
                    mmah(oacc[0][n], pa[0], bb);
                    mmah(oacc[1][n], pa[1], bb);
                }
            }
        }
        __syncthreads();
    }

    // ---- epilogue: normalize, write fp16 head slice ----
    __half* Og = g_oh + ((size_t)(b * TSEQ) + qb * 256) * DMODEL + h * DKH;
    #pragma unroll
    for (int mt = 0; mt < 2; ++mt) {
        const int r0 = wid * 32 + mt * 16 + r;
        const float i0 = 1.0f / lacc[mt][0], i1 = 1.0f / lacc[mt][2];
        #pragma unroll
        for (int n = 0; n < 8; ++n) {
            const int d = 8 * n + 2 * cl;
            *(half2*)&Og[(size_t)r0 * DMODEL + d] =
                __floats2half2_rn(oacc[mt][n][0] * i0, oacc[mt][n][1] * i0);
            *(half2*)&Og[(size_t)(r0 + 8) * DMODEL + d] =
                __floats2half2_rn(oacc[mt][n][2] * i1, oacc[mt][n][3] * i1);
        }
    }
}

// ---------------------------------------------------------------------------
extern "C" void kernel_launch(void* const* d_in, const int* in_sizes, int n_in,
                              void* d_out, int out_size)
{
    const float* x  = (const float*)d_in[0];
    float* out = (float*)d_out;
    (void)in_sizes; (void)n_in; (void)out_size;

    cudaFuncSetAttribute(qkv_gemm_kernel,
                         cudaFuncAttributeMaxDynamicSharedMemorySize, GEMM_SMEM);
    cudaFuncSetAttribute(proj_gemm_kernel,
                         cudaFuncAttributeMaxDynamicSharedMemorySize, GEMM_SMEM);
    cudaFuncSetAttribute(flash_kernel,
                         cudaFuncAttributeMaxDynamicSharedMemorySize, FLASH_SMEM);

    cvt_all_kernel<<<(CVT_TOT + 255) / 256, 256>>>(
        x, (const float*)d_in[1], (const float*)d_in[2],
        (const float*)d_in[3], (const float*)d_in[4]);

    qkv_gemm_kernel<<<dim3(MTOT / 128, DMODEL / 128, 3), 256, GEMM_SMEM>>>(0);
    flash_kernel<<<dim3(TSEQ / 256, NHEADS, NBATCH), 256, FLASH_SMEM>>>();
    proj_gemm_kernel<<<dim3(MTOT / 128, DMODEL / 128, 1), 256, GEMM_SMEM>>>(out);
}

// round 10
// speedup vs baseline: 1.1776x; 1.1776x over previous
#include <cuda_runtime.h>
#include <cuda_fp16.h>

#define TSEQ   4096
#define DMODEL 512
#define NHEADS 8
#define DKH    64
#define NBATCH 2
#define MTOT   (NBATCH*TSEQ)          // 8192
// 1/sqrt(64) * log2(e): folded into Q so S is in log2 domain -> p = exp2(S)
#define QSC    0.1803368801111601f

// Scratch (allocation-free rule: static device globals)
__device__ __half g_xh[(size_t)MTOT*DMODEL];              // x in fp16
__device__ __half g_wh[4][(size_t)DMODEL*DMODEL];         // Wq,Wk,Wv,Wo in fp16
__device__ __half g_qh[(size_t)NBATCH*NHEADS*TSEQ*DKH];   // [B,H,T,dk] fp16 (Q pre-scaled)
__device__ __half g_kh[(size_t)NBATCH*NHEADS*TSEQ*DKH];
__device__ __half g_vh[(size_t)NBATCH*NHEADS*TSEQ*DKH];
__device__ __half g_oh[(size_t)MTOT*DMODEL];              // attention out fp16

__device__ __forceinline__ void mmah(float* d, const unsigned* a, const unsigned* b) {
    asm("mma.sync.aligned.m16n8k16.row.col.f32.f16.f16.f32 "
        "{%0,%1,%2,%3},{%4,%5,%6,%7},{%8,%9},{%0,%1,%2,%3};"
        : "+f"(d[0]), "+f"(d[1]), "+f"(d[2]), "+f"(d[3])
        : "r"(a[0]), "r"(a[1]), "r"(a[2]), "r"(a[3]), "r"(b[0]), "r"(b[1]));
}

// fp16-accumulator variant: C/D are 2 regs of packed half2 (rows r / r+8,
// col pairs (2cl, 2cl+1)) — exactly the PV A-fragment k-pair layout.
__device__ __forceinline__ void mmah16(unsigned* d, const unsigned* a, const unsigned* b) {
    asm("mma.sync.aligned.m16n8k16.row.col.f16.f16.f16.f16 "
        "{%0,%1},{%2,%3,%4,%5},{%6,%7},{%0,%1};"
        : "+r"(d[0]), "+r"(d[1])
        : "r"(a[0]), "r"(a[1]), "r"(a[2]), "r"(a[3]), "r"(b[0]), "r"(b[1]));
}

__device__ __forceinline__ unsigned h2exp2u(unsigned x) {
    unsigned r;
    asm("ex2.approx.f16x2 %0, %1;" : "=r"(r) : "r"(x));
    return r;
}

__device__ __forceinline__ void ldm_x4(unsigned* q, unsigned addr) {
    asm volatile("ldmatrix.sync.aligned.m8n8.x4.shared.b16 {%0,%1,%2,%3}, [%4];"
                 : "=r"(q[0]), "=r"(q[1]), "=r"(q[2]), "=r"(q[3]) : "r"(addr));
}
__device__ __forceinline__ void ldm_x2(unsigned& b0, unsigned& b1, unsigned addr) {
    asm volatile("ldmatrix.sync.aligned.m8n8.x2.shared.b16 {%0,%1}, [%2];"
                 : "=r"(b0), "=r"(b1) : "r"(addr));
}
__device__ __forceinline__ void ldm_x2_t(unsigned& b0, unsigned& b1, unsigned addr) {
    asm volatile("ldmatrix.sync.aligned.m8n8.x2.trans.shared.b16 {%0,%1}, [%2];"
                 : "=r"(b0), "=r"(b1) : "r"(addr));
}

#define CP_ASYNC16(dst, src) \
    asm volatile("cp.async.ca.shared.global [%0], [%1], 16;" :: "r"(dst), "l"(src) : "memory")
#define CP_COMMIT   asm volatile("cp.async.commit_group;" ::: "memory")
#define CP_WAIT0    asm volatile("cp.async.wait_group 0;" ::: "memory")
#define CP_WAIT1    asm volatile("cp.async.wait_group 1;" ::: "memory")

// ---------------------------------------------------------------------------
// Fused fp32 -> fp16 conversion: x + 4 weights
// ---------------------------------------------------------------------------
#define XF4 (MTOT * DMODEL / 4)        // 1048576
#define WF4 (DMODEL * DMODEL / 4)      // 65536
#define CVT_TOT (XF4 + 4 * WF4)

__global__ __launch_bounds__(256)
void cvt_all_kernel(const float* __restrict__ x,
                    const float* __restrict__ w0, const float* __restrict__ w1,
                    const float* __restrict__ w2, const float* __restrict__ w3)
{
    const int i = blockIdx.x * 256 + threadIdx.x;
    if (i >= CVT_TOT) return;
    const float* s;
    __half* d;
    int off;
    if (i < XF4) {
        s = x; d = g_xh; off = i;
    } else {
        const int j = i - XF4;
        const int wsel = j >> 16;
        off = j & (WF4 - 1);
        s = (wsel == 0) ? w0 : (wsel == 1) ? w1 : (wsel == 2) ? w2 : w3;
        d = g_wh[wsel];
    }
    const float4 v = *(const float4*)(s + 4 * (size_t)off);
    half2 a = __floats2half2_rn(v.x, v.y);
    half2 b = __floats2half2_rn(v.z, v.w);
    *(uint2*)(d + 4 * (size_t)off) = make_uint2(*(unsigned*)&a, *(unsigned*)&b);
}

// ---------------------------------------------------------------------------
// fp16 NT GEMM body (unchanged): CTA 128x128, BK=64, 8 warps, m16n8k16,
// cp.async double-buffered, stride-72 smem rows.
// ---------------------------------------------------------------------------
#define GSTRH 72
#define GTILE (128 * GSTRH)
#define GEMM_SMEM (4 * GTILE * 2)      // 73728 B

__device__ __forceinline__ void gemm_body_fp16(
    const __half* __restrict__ A, const __half* __restrict__ W,
    float (&acc)[4][4][4], __half* smh, int m0, int n0, int tid)
{
    const unsigned smb = (unsigned)__cvta_generic_to_shared(smh);
    const int lane = tid & 31, wid = tid >> 5;
    const int wm = wid >> 2, wn = wid & 3;
    const int l15 = lane & 15, l16 = lane >> 4;
    const int l7 = lane & 7,  l8 = (lane >> 3) & 1;

    const int crow = tid >> 1;
    const int cseg = (tid & 1) * 32;

    const __half* Asrc = A + (size_t)(m0 + crow) * DMODEL + cseg;
    const __half* Wsrc = W + (size_t)(n0 + crow) * DMODEL + cseg;
    const unsigned adst = smb + (unsigned)(crow * GSTRH + cseg) * 2;
    const unsigned bdst = adst + GTILE * 2;

    #pragma unroll
    for (int i = 0; i < 4; ++i) {
        CP_ASYNC16(adst + 16 * i, Asrc + 8 * i);
        CP_ASYNC16(bdst + 16 * i, Wsrc + 8 * i);
    }
    CP_COMMIT;

    const unsigned afl = (unsigned)(l15 * GSTRH + l16 * 8) * 2;
    const unsigned bfl = (unsigned)(l7 * GSTRH + l8 * 8) * 2;

    const int NK = DMODEL / 64;
    for (int ks = 0; ks < NK; ++ks) {
        const int st = ks & 1;
        if (ks + 1 < NK) {
            const unsigned base = smb + (unsigned)(st ^ 1) * (2 * GTILE * 2);
            const unsigned ad = base + (unsigned)(crow * GSTRH + cseg) * 2;
            const unsigned bd = ad + GTILE * 2;
            const __half* as = Asrc + (ks + 1) * 64;
            const __half* ws = Wsrc + (ks + 1) * 64;
            #pragma unroll
            for (int i = 0; i < 4; ++i) {
                CP_ASYNC16(ad + 16 * i, as + 8 * i);
                CP_ASYNC16(bd + 16 * i, ws + 8 * i);
            }
            CP_COMMIT;
            CP_WAIT1;
        } else {
            CP_WAIT0;
        }
        __syncthreads();

        const unsigned abase = smb + (unsigned)st * (2 * GTILE * 2);
        const unsigned bbase = abase + GTILE * 2;

        #pragma unroll
        for (int kc = 0; kc < 4; ++kc) {
            unsigned a[4][4], b[4][2];
            #pragma unroll
            for (int mt = 0; mt < 4; ++mt)
                ldm_x4(a[mt], abase + (unsigned)((wm * 64 + mt * 16) * GSTRH + kc * 16) * 2 + afl);
            #pragma unroll
            for (int nt = 0; nt < 4; ++nt)
                ldm_x2(b[nt][0], b[nt][1],
                       bbase + (unsigned)((wn * 32 + nt * 8) * GSTRH + kc * 16) * 2 + bfl);
            #pragma unroll
            for (int mt = 0; mt < 4; ++mt)
                #pragma unroll
                for (int nt = 0; nt < 4; ++nt)
                    mmah(acc[mt][nt], a[mt], b[nt]);
        }
        __syncthreads();
    }
}

__global__ __launch_bounds__(256, 2)
void qkv_gemm_kernel(int dummy)
{
    extern __shared__ __half smh[];
    const __half* W = g_wh[blockIdx.z];
    __half* dst = (blockIdx.z == 0) ? g_qh : (blockIdx.z == 1) ? g_kh : g_vh;
    const float sc = (blockIdx.z == 0) ? QSC : 1.0f;

    const int tid = threadIdx.x;
    const int lane = tid & 31, wid = tid >> 5;
    const int wm = wid >> 2, wn = wid & 3;
    const int r = lane >> 2, cl = lane & 3;
    const int m0 = blockIdx.x * 128, n0 = blockIdx.y * 128;

    float acc[4][4][4] = {};
    gemm_body_fp16(g_xh, W, acc, smh, m0, n0, tid);

    #pragma unroll
    for (int mt = 0; mt < 4; ++mt) {
        #pragma unroll
        for (int half_ = 0; half_ < 2; ++half_) {
            const int m = m0 + wm * 64 + mt * 16 + r + half_ * 8;
            const int b = m >> 12;
            const int t = m & 4095;
            #pragma unroll
            for (int nt = 0; nt < 4; ++nt) {
                const int n = n0 + wn * 32 + nt * 8 + 2 * cl;
                const int h = n >> 6, d = n & 63;
                const float vx = (half_ ? acc[mt][nt][2] : acc[mt][nt][0]) * sc;
                const float vy = (half_ ? acc[mt][nt][3] : acc[mt][nt][1]) * sc;
                *(half2*)&dst[(((size_t)(b * NHEADS + h) * TSEQ) + t) * DKH + d] =
                    __floats2half2_rn(vx, vy);
            }
        }
    }
    (void)dummy;
}

__global__ __launch_bounds__(256, 2)
void proj_gemm_kernel(float* __restrict__ out)
{
    extern __shared__ __half smh[];
    const int tid = threadIdx.x;
    const int lane = tid & 31, wid = tid >> 5;
    const int wm = wid >> 2, wn = wid & 3;
    const int r = lane >> 2, cl = lane & 3;
    const int m0 = blockIdx.x * 128, n0 = blockIdx.y * 128;

    float acc[4][4][4] = {};
    gemm_body_fp16(g_oh, g_wh[3], acc, smh, m0, n0, tid);

    #pragma unroll
    for (int mt = 0; mt < 4; ++mt) {
        const int m = m0 + wm * 64 + mt * 16 + r;
        #pragma unroll
        for (int nt = 0; nt < 4; ++nt) {
            const int n = n0 + wn * 32 + nt * 8 + 2 * cl;
            *(float2*)&out[(size_t)m * DMODEL + n] =
                make_float2(acc[mt][nt][0], acc[mt][nt][1]);
            *(float2*)&out[(size_t)(m + 8) * DMODEL + n] =
                make_float2(acc[mt][nt][2], acc[mt][nt][3]);
        }
    }
}

// ---------------------------------------------------------------------------
// Flash attention, fully-fp16 score path, occupancy 1 (NO register cap —
// round 9 showed the 128-reg cap from minBlocks=2 spills and regresses):
//   S accumulated in fp16 (packed C-frags == PV A-frag layout, zero reshapes)
//   p = ex2.approx.f16x2(S)  (S in log2 domain via QSC)
//   row sums li via ones-MMA with fp32 accumulate
// Br=256 (8 warps x 32 rows), Bc=128, cp.async double-buffered.
// ---------------------------------------------------------------------------
#define HSTR 72
#define BUFH (256 * HSTR)
#define FLASH_SMEM (2 * BUFH * 2)      // 73728 B
#define ONES_H2 0x3C003C00u            // half2(1.0, 1.0)

__global__ __launch_bounds__(256, 1)
void flash_kernel()
{
    extern __shared__ __half smh[];
    const unsigned smb = (unsigned)__cvta_generic_to_shared(smh);

    const int tid  = threadIdx.x;
    const int lane = tid & 31, wid = tid >> 5;
    const int r = lane >> 2, cl = lane & 3;
    const int l7 = lane & 7, l8 = (lane >> 3) & 1;
    const int qb = blockIdx.x, h = blockIdx.y, b = blockIdx.z;

    const __half* Qg = g_qh + (((size_t)(b * NHEADS + h) * TSEQ) + qb * 256) * DKH;
    const __half* Kg = g_kh + ((size_t)(b * NHEADS + h) * TSEQ) * DKH;
    const __half* Vg = g_vh + ((size_t)(b * NHEADS + h) * TSEQ) * DKH;

    // ---- stage Q tile (256x64 fp16), extract A-frags ----
    {
        const uint4* qsrc = (const uint4*)(Qg + (size_t)tid * DKH);
        uint4* qdst = (uint4*)(smh + tid * HSTR);
        #pragma unroll
        for (int i = 0; i < 8; ++i) qdst[i] = qsrc[i];
    }
    __syncthreads();

    unsigned qa[2][4][4];
    #pragma unroll
    for (int mt = 0; mt < 2; ++mt) {
        const int row = wid * 32 + mt * 16 + r;
        #pragma unroll
        for (int kc = 0; kc < 4; ++kc) {
            qa[mt][kc][0] = *(const unsigned*)&smh[row * HSTR + 16 * kc + 2 * cl];
            qa[mt][kc][1] = *(const unsigned*)&smh[(row + 8) * HSTR + 16 * kc + 2 * cl];
            qa[mt][kc][2] = *(const unsigned*)&smh[row * HSTR + 16 * kc + 2 * cl + 8];
            qa[mt][kc][3] = *(const unsigned*)&smh[(row + 8) * HSTR + 16 * kc + 2 * cl + 8];
        }
    }
    __syncthreads();

    const int crow = tid & 127;
    const bool isV = tid >= 128;
    const __half* gsrc0 = isV ? Vg : Kg;
    const unsigned dst_off = ((isV ? 128 * HSTR : 0) + crow * HSTR) * 2;

    {   // prologue
        const __half* src = gsrc0 + (size_t)crow * DKH;
        const unsigned d0 = smb + dst_off;
        #pragma unroll
        for (int i = 0; i < 8; ++i) CP_ASYNC16(d0 + 16 * i, src + 8 * i);
        CP_COMMIT;
    }

    float oacc[2][8][4] = {};
    float lacc[2][4] = {};
    const unsigned onesb[2] = {ONES_H2, ONES_H2};

    const unsigned kla = (unsigned)(l7 * HSTR + l8 * 8) * 2;
    const unsigned vla = (unsigned)((l7 + 8 * l8) * HSTR) * 2;

    const int NT = TSEQ / 128;
    for (int kt = 0; kt < NT; ++kt) {
        const int bf = kt & 1;
        if (kt + 1 < NT) {
            const __half* src = gsrc0 + (size_t)((kt + 1) * 128 + crow) * DKH;
            const unsigned d0 = smb + (unsigned)(bf ^ 1) * (BUFH * 2) + dst_off;
            #pragma unroll
            for (int i = 0; i < 8; ++i) CP_ASYNC16(d0 + 16 * i, src + 8 * i);
            CP_COMMIT;
            CP_WAIT1;
        } else {
            CP_WAIT0;
        }
        __syncthreads();

        const unsigned kbase = smb + (unsigned)bf * (BUFH * 2);
        const unsigned vbase = kbase + 128 * HSTR * 2;

        #pragma unroll
        for (int ch = 0; ch < 2; ++ch) {
            // ---- S chunk (log2 domain), fp16 accumulators ----
            unsigned sacc[2][8][2] = {};
            #pragma unroll
            for (int t = 0; t < 8; ++t) {
                const unsigned rowb = kbase + (unsigned)((64 * ch + 8 * t) * HSTR) * 2 + kla;
                #pragma unroll
                for (int kc = 0; kc < 4; ++kc) {
                    unsigned bb[2];
                    ldm_x2(bb[0], bb[1], rowb + 32 * kc);
                    mmah16(sacc[0][t], qa[0][kc], bb);
                    mmah16(sacc[1][t], qa[1][kc], bb);
                }
            }

            // ---- PV: pa = exp2(S) straight from packed C-frags ----
            #pragma unroll
            for (int kc = 0; kc < 4; ++kc) {
                unsigned pa[2][4];
                #pragma unroll
                for (int mt = 0; mt < 2; ++mt) {
                    pa[mt][0] = h2exp2u(sacc[mt][2*kc][0]);
                    pa[mt][1] = h2exp2u(sacc[mt][2*kc][1]);
                    pa[mt][2] = h2exp2u(sacc[mt][2*kc + 1][0]);
                    pa[mt][3] = h2exp2u(sacc[mt][2*kc + 1][1]);
                }
                mmah(lacc[0], pa[0], onesb);
                mmah(lacc[1], pa[1], onesb);
                const unsigned vrow = vbase + (unsigned)((64 * ch + 16 * kc) * HSTR) * 2 + vla;
                #pragma unroll
                for (int n = 0; n < 8; ++n) {
                    unsigned bb[2];
                    ldm_x2_t(bb[0], bb[1], vrow + 16 * n);
                    mmah(oacc[0][n], pa[0], bb);
                    mmah(oacc[1][n], pa[1], bb);
                }
            }
        }
        __syncthreads();
    }

    // ---- epilogue: normalize, write fp16 head slice ----
    __half* Og = g_oh + ((size_t)(b * TSEQ) + qb * 256) * DMODEL + h * DKH;
    #pragma unroll
    for (int mt = 0; mt < 2; ++mt) {
        const int r0 = wid * 32 + mt * 16 + r;
        const float i0 = 1.0f / lacc[mt][0], i1 = 1.0f / lacc[mt][2];
        #pragma unroll
        for (int n = 0; n < 8; ++n) {
            const int d = 8 * n + 2 * cl;
            *(half2*)&Og[(size_t)r0 * DMODEL + d] =
                __floats2half2_rn(oacc[mt][n][0] * i0, oacc[mt][n][1] * i0);
            *(half2*)&Og[(size_t)(r0 + 8) * DMODEL + d] =
                __floats2half2_rn(oacc[mt][n][2] * i1, oacc[mt][n][3] * i1);
        }
    }
}

// ---------------------------------------------------------------------------
extern "C" void kernel_launch(void* const* d_in, const int* in_sizes, int n_in,
                              void* d_out, int out_size)
{
    const float* x  = (const float*)d_in[0];
    float* out = (float*)d_out;
    (void)in_sizes; (void)n_in; (void)out_size;

    cudaFuncSetAttribute(qkv_gemm_kernel,
                         cudaFuncAttributeMaxDynamicSharedMemorySize, GEMM_SMEM);
    cudaFuncSetAttribute(proj_gemm_kernel,
                         cudaFuncAttributeMaxDynamicSharedMemorySize, GEMM_SMEM);
    cudaFuncSetAttribute(flash_kernel,
                         cudaFuncAttributeMaxDynamicSharedMemorySize, FLASH_SMEM);

    cvt_all_kernel<<<(CVT_TOT + 255) / 256, 256>>>(
        x, (const float*)d_in[1], (const float*)d_in[2],
        (const float*)d_in[3], (const float*)d_in[4]);

    qkv_gemm_kernel<<<dim3(MTOT / 128, DMODEL / 128, 3), 256, GEMM_SMEM>>>(0);
    flash_kernel<<<dim3(TSEQ / 256, NHEADS, NBATCH), 256, FLASH_SMEM>>>();
    proj_gemm_kernel<<<dim3(MTOT / 128, DMODEL / 128, 1), 256, GEMM_SMEM>>>(out);
}